// round 15
// baseline (speedup 1.0000x reference)
#include <cuda_runtime.h>
#include <stdint.h>
#include <math.h>

#define IMG_W 4096
#define IMG_H 4096
#define TW 64           // output tile width
#define TH 32           // output tile height
#define NT 256

// shared strides (floats), multiples of 4 for LDS.128
#define SA  76          // img tile stride
#define SBs 68          // bufB: h-blurred tmp 40x68
#define SBL 72          // bufBl: v-blurred 36x68 (stride 72 to fit 5 CTAs/SM)
#define SMs 72          // bufM view: 34 rows x 72 (aliases bufI0)

typedef unsigned long long ull;

__device__ __forceinline__ ull packf2(float a, float b)
{
    ull o;
    asm("mov.b64 %0, {%1, %2};" : "=l"(o) : "f"(a), "f"(b));
    return o;
}
__device__ __forceinline__ ull pmul(ull a, ull b)
{
    ull o;
    asm("mul.rn.f32x2 %0, %1, %2;" : "=l"(o) : "l"(a), "l"(b));
    return o;
}
__device__ __forceinline__ ull pfma(ull a, ull b, ull c)
{
    ull o;
    asm("fma.rn.f32x2 %0, %1, %2, %3;" : "=l"(o) : "l"(a), "l"(b), "l"(c));
    return o;
}

// packed 5-tap: g0*p0 + g1*p1 + g2*p2 + g3*p3 + g4*p4 (exact FFMA chain order)
__device__ __forceinline__ ull pblur5(ull G0, ull G1, ull G2, ull G3, ull G4,
                                      ull p0, ull p1, ull p2, ull p3, ull p4)
{
    return pfma(G4, p4, pfma(G3, p3, pfma(G2, p2, pfma(G1, p1, pmul(G0, p0)))));
}

__device__ __forceinline__ float4 vblur5(float g0, float g1, float g2, float g3, float g4,
                                         float4 a, float4 b, float4 c, float4 d, float4 e)
{
    float4 o;
    o.x = g0*a.x + g1*b.x + g2*c.x + g3*d.x + g4*e.x;
    o.y = g0*a.y + g1*b.y + g2*c.y + g3*d.y + g4*e.y;
    o.z = g0*a.z + g1*b.z + g2*c.z + g3*d.z + g4*e.z;
    o.w = g0*a.w + g1*b.w + g2*c.w + g3*d.w + g4*e.w;
    return o;
}

__device__ __forceinline__ void cp_async16(void* dst_smem, const void* src)
{
    unsigned int d = (unsigned int)__cvta_generic_to_shared(dst_smem);
    asm volatile("cp.async.cg.shared.global [%0], [%1], 16;" :: "r"(d), "l"(src));
}

__global__ __launch_bounds__(NT, 5) void canny_kernel(
    const float* __restrict__ img,
    const float* __restrict__ gauss,
    float* __restrict__ out)
{
    __shared__ __align__(16) float bufI0[40 * SA];   // img tile, channel even
    __shared__ __align__(16) float bufI1[40 * SA];   // img tile, channel odd
    __shared__ __align__(16) float bufB[40 * SBs];   // h-blurred
    __shared__ __align__(16) float bufBl[36 * SBL];  // v-blurred
    float* bufM = bufI0;                             // 34*SMs = 2448 <= 3040 floats

    const int tid = threadIdx.x;
    const int bx = blockIdx.x * TW;
    const int by = blockIdx.y * TH;
    const bool interior = (blockIdx.x >= 1 && blockIdx.x <= 62 &&
                           blockIdx.y >= 1 && blockIdx.y <= 126);

    const float g0 = gauss[0], g1 = gauss[1], g2 = gauss[2],
                g3 = gauss[3], g4 = gauss[4];
    const ull G0 = packf2(g0, g0), G1 = packf2(g1, g1), G2 = packf2(g2, g2),
              G3 = packf2(g3, g3), G4 = packf2(g4, g4);

    // this thread's 4-wide x 2-tall output patch
    const int ox = 4 * (tid & 15);
    const int oy = 2 * (tid >> 4);

    // ---- S1 prefetch mapping: 720 float4 (40 rows x 18) ----
    const int s1r0 = tid / 18,          s1c0 = (tid - s1r0 * 18) * 4;
    const int t1i = tid + 256;
    const int s1r1 = t1i / 18,          s1c1 = (t1i - s1r1 * 18) * 4;
    const int t2s = tid + 512;
    const int s1r2 = t2s / 18,          s1c2 = (t2s - s1r2 * 18) * 4;
    const bool s1b2 = (t2s < 720);      // 208 threads

    // ---- S2 mapping: wide patches (1 row x 8 outputs), 320 items ----
    const int r20 = 8 * (tid >> 6) + (tid & 7);
    const int j20 = 8 * ((tid >> 3) & 7);
    const int i1  = tid + 256;                    // valid for tid < 64
    const int r21 = 8 * (i1 >> 6) + (i1 & 7);
    const int j21 = 8 * ((i1 >> 3) & 7);
    const bool s2b = (tid < 64);
    const bool s2n = (tid >= 192 && tid < 232);   // narrow col, rows 0..39
    const int rn = tid - 192;

    // ---- S3 mapping: 4-row x 1-col4 patches, 153 items ----
    const bool s3ok = (tid < 153);
    const int r3 = 4 * (tid / 17);
    const int j3 = 4 * (tid % 17);

    // ring pixel (mag coords: rows {1,34} x cols 0..65, cols {0,65} x rows 2..33)
    int mr = 1, mc = 0;
    const bool has_ring = (tid < 196);
    if (tid < 66)       { mr = 1;         mc = tid; }
    else if (tid < 132) { mr = 34;        mc = tid - 66; }
    else if (tid < 164) { mr = tid - 130; mc = 0; }
    else if (tid < 196) { mr = tid - 162; mc = 65; }

    float gxa[8], gya[8], maga[8];
    #pragma unroll
    for (int i = 0; i < 8; i++) { gxa[i] = 0.0f; gya[i] = 0.0f; maga[i] = 0.0f; }
    float ring_m = 0.0f;

    // ---- initial prefetch: channel 0 -> bufI0 ----
    if (interior) {
        const float* base = img + (size_t)(by - 4) * IMG_W + (bx - 4);
        cp_async16(&bufI0[s1r0 * SA + s1c0], base + (size_t)s1r0 * IMG_W + s1c0);
        cp_async16(&bufI0[s1r1 * SA + s1c1], base + (size_t)s1r1 * IMG_W + s1c1);
        if (s1b2)
            cp_async16(&bufI0[s1r2 * SA + s1c2], base + (size_t)s1r2 * IMG_W + s1c2);
        asm volatile("cp.async.commit_group;");
    } else {
        for (int p = tid; p < 2880; p += NT) {
            int r = p / 72;
            int cc = p - r * 72;
            int iy = by - 4 + r, ix = bx - 4 + cc;
            float v = 0.0f;
            if (iy >= 0 && iy < IMG_H && ix >= 0 && ix < IMG_W)
                v = img[(size_t)iy * IMG_W + ix];
            bufI0[r * SA + cc] = v;
        }
    }

    #pragma unroll
    for (int c = 0; c < 3; c++) {
        float* bI = (c & 1) ? bufI1 : bufI0;

        asm volatile("cp.async.wait_group 0;");
        __syncthreads();                 // bI ready; also orders prior channel's
                                         // S4/S4r reads before this channel's writes

        // ---- prefetch next channel ----
        if (c < 2) {
            float* bN = ((c + 1) & 1) ? bufI1 : bufI0;
            const float* imn = img + (size_t)(c + 1) * (IMG_H * IMG_W);
            if (interior) {
                const float* base = imn + (size_t)(by - 4) * IMG_W + (bx - 4);
                cp_async16(&bN[s1r0 * SA + s1c0], base + (size_t)s1r0 * IMG_W + s1c0);
                cp_async16(&bN[s1r1 * SA + s1c1], base + (size_t)s1r1 * IMG_W + s1c1);
                if (s1b2)
                    cp_async16(&bN[s1r2 * SA + s1c2], base + (size_t)s1r2 * IMG_W + s1c2);
                asm volatile("cp.async.commit_group;");
            } else {
                for (int p = tid; p < 2880; p += NT) {
                    int r = p / 72;
                    int cc = p - r * 72;
                    int iy = by - 4 + r, ix = bx - 4 + cc;
                    float v = 0.0f;
                    if (iy >= 0 && iy < IMG_H && ix >= 0 && ix < IMG_W)
                        v = imn[(size_t)iy * IMG_W + ix];
                    bN[r * SA + cc] = v;
                }
            }
        }

        // ---- S2: horizontal gaussian -> bufB (40 rows x 68 cols), scalar ----
        {
            {
                const float* a = &bI[r20 * SA + j20];
                float4 v0 = *(const float4*)a;
                float4 v1 = *(const float4*)(a + 4);
                float4 v2 = *(const float4*)(a + 8);
                float w0=v0.x,w1=v0.y,w2=v0.z,w3=v0.w,w4=v1.x,w5=v1.y,w6=v1.z,w7=v1.w,
                      w8=v2.x,w9=v2.y,w10=v2.z,w11=v2.w;
                float4 o0, o1;
                o0.x = g0*w0 + g1*w1 + g2*w2 + g3*w3 + g4*w4;
                o0.y = g0*w1 + g1*w2 + g2*w3 + g3*w4 + g4*w5;
                o0.z = g0*w2 + g1*w3 + g2*w4 + g3*w5 + g4*w6;
                o0.w = g0*w3 + g1*w4 + g2*w5 + g3*w6 + g4*w7;
                o1.x = g0*w4 + g1*w5 + g2*w6 + g3*w7 + g4*w8;
                o1.y = g0*w5 + g1*w6 + g2*w7 + g3*w8 + g4*w9;
                o1.z = g0*w6 + g1*w7 + g2*w8 + g3*w9 + g4*w10;
                o1.w = g0*w7 + g1*w8 + g2*w9 + g3*w10 + g4*w11;
                *(float4*)&bufB[r20 * SBs + j20]     = o0;
                *(float4*)&bufB[r20 * SBs + j20 + 4] = o1;
            }
            if (s2b) {
                const float* a = &bI[r21 * SA + j21];
                float4 v0 = *(const float4*)a;
                float4 v1 = *(const float4*)(a + 4);
                float4 v2 = *(const float4*)(a + 8);
                float w0=v0.x,w1=v0.y,w2=v0.z,w3=v0.w,w4=v1.x,w5=v1.y,w6=v1.z,w7=v1.w,
                      w8=v2.x,w9=v2.y,w10=v2.z,w11=v2.w;
                float4 o0, o1;
                o0.x = g0*w0 + g1*w1 + g2*w2 + g3*w3 + g4*w4;
                o0.y = g0*w1 + g1*w2 + g2*w3 + g3*w4 + g4*w5;
                o0.z = g0*w2 + g1*w3 + g2*w4 + g3*w5 + g4*w6;
                o0.w = g0*w3 + g1*w4 + g2*w5 + g3*w6 + g4*w7;
                o1.x = g0*w4 + g1*w5 + g2*w6 + g3*w7 + g4*w8;
                o1.y = g0*w5 + g1*w6 + g2*w7 + g3*w8 + g4*w9;
                o1.z = g0*w6 + g1*w7 + g2*w8 + g3*w9 + g4*w10;
                o1.w = g0*w7 + g1*w8 + g2*w9 + g3*w10 + g4*w11;
                *(float4*)&bufB[r21 * SBs + j21]     = o0;
                *(float4*)&bufB[r21 * SBs + j21 + 4] = o1;
            }
            if (s2n) {
                const float* a = &bI[rn * SA + 64];
                float4 v0 = *(const float4*)a;
                float4 v1 = *(const float4*)(a + 4);
                float4 o0;
                o0.x = g0*v0.x + g1*v0.y + g2*v0.z + g3*v0.w + g4*v1.x;
                o0.y = g0*v0.y + g1*v0.z + g2*v0.w + g3*v1.x + g4*v1.y;
                o0.z = g0*v0.z + g1*v0.w + g2*v1.x + g3*v1.y + g4*v1.z;
                o0.w = g0*v0.w + g1*v1.x + g2*v1.y + g3*v1.z + g4*v1.w;
                *(float4*)&bufB[rn * SBs + 64] = o0;
            }
        }
        __syncthreads();

        // ---- S3: vertical gaussian -> bufBl (36 rows x 68 cols), 4-row patch ----
        if (s3ok) {
            const float* bcol = &bufB[r3 * SBs + j3];
            float* acol = &bufBl[r3 * SBL + j3];
            if (interior) {
                // packed f32x2: 10 ops per float4 instead of 20
                ulonglong2 t0 = *(const ulonglong2*)(bcol);
                ulonglong2 t1 = *(const ulonglong2*)(bcol + 1 * SBs);
                ulonglong2 t2 = *(const ulonglong2*)(bcol + 2 * SBs);
                ulonglong2 t3 = *(const ulonglong2*)(bcol + 3 * SBs);
                ulonglong2 t4 = *(const ulonglong2*)(bcol + 4 * SBs);
                #pragma unroll
                for (int k = 0; k < 4; k++) {
                    ulonglong2 o;
                    o.x = pblur5(G0, G1, G2, G3, G4, t0.x, t1.x, t2.x, t3.x, t4.x);
                    o.y = pblur5(G0, G1, G2, G3, G4, t0.y, t1.y, t2.y, t3.y, t4.y);
                    *(ulonglong2*)(acol + k * SBL) = o;
                    if (k < 3) {
                        t0 = t1; t1 = t2; t2 = t3; t3 = t4;
                        t4 = *(const ulonglong2*)(bcol + (5 + k) * SBs);
                    }
                }
            } else {
                float4 t0 = *(const float4*)(bcol);
                float4 t1 = *(const float4*)(bcol + 1 * SBs);
                float4 t2 = *(const float4*)(bcol + 2 * SBs);
                float4 t3 = *(const float4*)(bcol + 3 * SBs);
                float4 t4 = *(const float4*)(bcol + 4 * SBs);
                #pragma unroll
                for (int k = 0; k < 4; k++) {
                    float4 o = vblur5(g0, g1, g2, g3, g4, t0, t1, t2, t3, t4);
                    int iy = by - 2 + r3 + k;
                    int ixb = bx - 2 + j3;
                    float* po = &o.x;
                    #pragma unroll
                    for (int cc = 0; cc < 4; cc++) {
                        int ix = ixb + cc;
                        if (!(ix >= 0 && ix < IMG_W && iy >= 0 && iy < IMG_H)) po[cc] = 0.0f;
                    }
                    *(float4*)(acol + k * SBL) = o;
                    if (k < 3) {
                        t0 = t1; t1 = t2; t2 = t3; t3 = t4;
                        t4 = *(const float4*)(bcol + (5 + k) * SBs);
                    }
                }
            }
        }
        __syncthreads();

        // ---- S4: sobel at output patch -> register accumulators ----
        // at c==2 the final mag is also stored straight to bufM (aliases bufI0,
        // whose last reads -- S2 of c==2 -- completed before the post-S2 barrier)
        {
            const float* b = &bufBl[(oy + 1) * SBL + ox];
            float r0[8], r1[8], r2[8], r3v[8];
            {
                float4 lo, hi;
                lo = *(const float4*)(b);            hi = *(const float4*)(b + 4);
                r0[0]=lo.x; r0[1]=lo.y; r0[2]=lo.z; r0[3]=lo.w; r0[4]=hi.x; r0[5]=hi.y; r0[6]=hi.z; r0[7]=hi.w;
                lo = *(const float4*)(b + SBL);      hi = *(const float4*)(b + SBL + 4);
                r1[0]=lo.x; r1[1]=lo.y; r1[2]=lo.z; r1[3]=lo.w; r1[4]=hi.x; r1[5]=hi.y; r1[6]=hi.z; r1[7]=hi.w;
                lo = *(const float4*)(b + 2*SBL);    hi = *(const float4*)(b + 2*SBL + 4);
                r2[0]=lo.x; r2[1]=lo.y; r2[2]=lo.z; r2[3]=lo.w; r2[4]=hi.x; r2[5]=hi.y; r2[6]=hi.z; r2[7]=hi.w;
            }
            #pragma unroll
            for (int cc = 0; cc < 4; cc++) {
                float b00 = r0[cc+1], b01 = r0[cc+2], b02 = r0[cc+3];
                float b10 = r1[cc+1],                 b12 = r1[cc+3];
                float b20 = r2[cc+1], b21 = r2[cc+2], b22 = r2[cc+3];
                float gxv = (b00 - b02) + 2.0f * (b10 - b12) + (b20 - b22);
                float gyv = (b00 - b20) + 2.0f * (b01 - b21) + (b02 - b22);
                gxa[cc] += gxv;
                gya[cc] += gyv;
                maga[cc] += sqrtf(gxv * gxv + gyv * gyv + 1e-8f);
            }
            {
                float4 lo = *(const float4*)(b + 3*SBL);
                float4 hi = *(const float4*)(b + 3*SBL + 4);
                r3v[0]=lo.x; r3v[1]=lo.y; r3v[2]=lo.z; r3v[3]=lo.w; r3v[4]=hi.x; r3v[5]=hi.y; r3v[6]=hi.z; r3v[7]=hi.w;
            }
            #pragma unroll
            for (int cc = 0; cc < 4; cc++) {
                float b00 = r1[cc+1], b01 = r1[cc+2], b02 = r1[cc+3];
                float b10 = r2[cc+1],                 b12 = r2[cc+3];
                float b20 = r3v[cc+1], b21 = r3v[cc+2], b22 = r3v[cc+3];
                float gxv = (b00 - b02) + 2.0f * (b10 - b12) + (b20 - b22);
                float gyv = (b00 - b20) + 2.0f * (b01 - b21) + (b02 - b22);
                gxa[4+cc] += gxv;
                gya[4+cc] += gyv;
                maga[4+cc] += sqrtf(gxv * gxv + gyv * gyv + 1e-8f);
            }
            if (c == 2) {
                *(float4*)&bufM[(oy + 1) * SMs + ox + 4] =
                    make_float4(maga[0], maga[1], maga[2], maga[3]);
                *(float4*)&bufM[(oy + 2) * SMs + ox + 4] =
                    make_float4(maga[4], maga[5], maga[6], maga[7]);
            }
        }

        // ---- S4r: halo-ring mag pixel (register accumulated) ----
        if (has_ring) {
            const float* b = &bufBl[(mr - 1) * SBL + mc];
            float b00 = b[0],       b01 = b[1],           b02 = b[2];
            float b10 = b[SBL],                           b12 = b[SBL + 2];
            float b20 = b[2 * SBL], b21 = b[2 * SBL + 1], b22 = b[2 * SBL + 2];
            float gxv = (b00 - b02) + 2.0f * (b10 - b12) + (b20 - b22);
            float gyv = (b00 - b20) + 2.0f * (b01 - b21) + (b02 - b22);
            float m = sqrtf(gxv * gxv + gyv * gyv + 1e-8f);
            if (!interior) {
                int iy = by - 2 + mr, ix = bx - 1 + mc;
                if (iy < 0 || iy >= IMG_H || ix < 0 || ix >= IMG_W) m = 0.0f;
            }
            ring_m += m;
            if (c == 2) bufM[(mr - 1) * SMs + mc + 3] = ring_m;
        }
        // no end-of-channel barrier (loop-top barrier provides the ordering)
    }

    __syncthreads();   // bufM fully published before S5 reads

    // ---- S5: octant classification, NMS, threshold, write ----
    // k = rint((atan2(gy,gx)*(180/3.14159)+180)/45) reproduced by sign/tan tests.
    //   t1 = tan(22.5*3.14159/180), t2 = tan(67.5*3.14159/180)
    // packed NMS offset table: d = dy*SMs + dx, stored as byte (d + 128)
    const ull DTAB = 0x3938377FC7C8C981ULL;
    const float T1 = 0.41421317f;
    const float T2 = 2.4142068f;

    #pragma unroll
    for (int rr = 0; rr < 2; rr++) {
        float ov[4];
        #pragma unroll
        for (int cc = 0; cc < 4; cc++) {
            int y = oy + rr, x = ox + cc;
            float m  = maga[rr*4+cc];
            float gx = gxa[rr*4+cc], gy = gya[rr*4+cc];
            float ax = fabsf(gx), ay = fabsf(gy);
            bool b2 = ay > T2 * ax;
            bool b1 = ay > T1 * ax;
            int o;
            if (b2)      o = 2;
            else if (b1) o = (gx < 0.0f) ? 3 : 1;
            else         o = (gx < 0.0f) ? 4 : 0;
            int k = (gy < 0.0f) ? (4 - o) : (4 + o);
            int ip = k & 7;
            int d = (int)((DTAB >> (ip * 8)) & 0xFF) - 128;
            int base = (y + 1) * SMs + (x + 4);
            float mp = bufM[base + d];
            float mn = bufM[base - d];
            bool is_max = fminf(m - mp, m - mn) > 0.0f;
            ov[cc] = (is_max && m >= 6.0f && m <= 50.0f) ? 1.0f : 0.0f;
        }
        *(float4*)(out + (size_t)(by + oy + rr) * IMG_W + bx + ox) =
            make_float4(ov[0], ov[1], ov[2], ov[3]);
    }
}

extern "C" void kernel_launch(void* const* d_in, const int* in_sizes, int n_in,
                              void* d_out, int out_size) {
    const float* img   = (const float*)d_in[0];  // [1,3,4096,4096]
    const float* gauss = (const float*)d_in[1];  // [5]
    float* out = (float*)d_out;                  // [1,1,4096,4096]

    dim3 grid(IMG_W / TW, IMG_H / TH);
    canny_kernel<<<grid, NT>>>(img, gauss, out);
}

// round 16
// speedup vs baseline: 1.1715x; 1.1715x over previous
#include <cuda_runtime.h>
#include <stdint.h>
#include <math.h>

#define IMG_W 4096
#define IMG_H 4096
#define TW 64           // output tile width
#define TH 32           // output tile height
#define NT 256

// shared strides (floats), multiples of 4 for LDS.128
#define SA  76          // img tiles + blur buffer stride
#define SBs 68          // bufB: h-blurred tmp 40x68
#define SMs 72          // bufM view: 34 rows x 72 (aliases bufI0)

typedef unsigned long long ull;

__device__ __forceinline__ ull packf2(float a, float b)
{
    ull o;
    asm("mov.b64 %0, {%1, %2};" : "=l"(o) : "f"(a), "f"(b));
    return o;
}
__device__ __forceinline__ ull pmul(ull a, ull b)
{
    ull o;
    asm("mul.rn.f32x2 %0, %1, %2;" : "=l"(o) : "l"(a), "l"(b));
    return o;
}
__device__ __forceinline__ ull pfma(ull a, ull b, ull c)
{
    ull o;
    asm("fma.rn.f32x2 %0, %1, %2, %3;" : "=l"(o) : "l"(a), "l"(b), "l"(c));
    return o;
}

// packed 5-tap: g0*p0 + g1*p1 + g2*p2 + g3*p3 + g4*p4 (exact FFMA chain order)
__device__ __forceinline__ ull pblur5(ull G0, ull G1, ull G2, ull G3, ull G4,
                                      ull p0, ull p1, ull p2, ull p3, ull p4)
{
    return pfma(G4, p4, pfma(G3, p3, pfma(G2, p2, pfma(G1, p1, pmul(G0, p0)))));
}

__device__ __forceinline__ float4 vblur5(float g0, float g1, float g2, float g3, float g4,
                                         float4 a, float4 b, float4 c, float4 d, float4 e)
{
    float4 o;
    o.x = g0*a.x + g1*b.x + g2*c.x + g3*d.x + g4*e.x;
    o.y = g0*a.y + g1*b.y + g2*c.y + g3*d.y + g4*e.y;
    o.z = g0*a.z + g1*b.z + g2*c.z + g3*d.z + g4*e.z;
    o.w = g0*a.w + g1*b.w + g2*c.w + g3*d.w + g4*e.w;
    return o;
}

__device__ __forceinline__ void cp_async16(void* dst_smem, const void* src)
{
    unsigned int d = (unsigned int)__cvta_generic_to_shared(dst_smem);
    asm volatile("cp.async.cg.shared.global [%0], [%1], 16;" :: "r"(d), "l"(src));
}

__global__ __launch_bounds__(NT, 4) void canny_kernel(
    const float* __restrict__ img,
    const float* __restrict__ gauss,
    float* __restrict__ out)
{
    __shared__ __align__(16) float bufI0[40 * SA];   // img tile, channel even
    __shared__ __align__(16) float bufI1[40 * SA];   // img tile, channel odd
    __shared__ __align__(16) float bufB[40 * SBs];   // h-blurred
    __shared__ __align__(16) float bufBl[36 * SA];   // v-blurred
    float* bufM = bufI0;                             // 34*SMs = 2448 <= 3040 floats

    const int tid = threadIdx.x;
    const int bx = blockIdx.x * TW;
    const int by = blockIdx.y * TH;
    const bool interior = (blockIdx.x >= 1 && blockIdx.x <= 62 &&
                           blockIdx.y >= 1 && blockIdx.y <= 126);

    const float g0 = gauss[0], g1 = gauss[1], g2 = gauss[2],
                g3 = gauss[3], g4 = gauss[4];
    const ull G0 = packf2(g0, g0), G1 = packf2(g1, g1), G2 = packf2(g2, g2),
              G3 = packf2(g3, g3), G4 = packf2(g4, g4);

    // this thread's 4-wide x 2-tall output patch
    const int ox = 4 * (tid & 15);
    const int oy = 2 * (tid >> 4);

    // ---- S1 prefetch mapping: 720 float4 (40 rows x 18) ----
    const int s1r0 = tid / 18,          s1c0 = (tid - s1r0 * 18) * 4;
    const int t1i = tid + 256;
    const int s1r1 = t1i / 18,          s1c1 = (t1i - s1r1 * 18) * 4;
    const int t2s = tid + 512;
    const int s1r2 = t2s / 18,          s1c2 = (t2s - s1r2 * 18) * 4;
    const bool s1b2 = (t2s < 720);      // 208 threads

    // ---- S2 mapping: wide patches (1 row x 8 outputs), 320 items ----
    const int r20 = 8 * (tid >> 6) + (tid & 7);
    const int j20 = 8 * ((tid >> 3) & 7);
    const int i1  = tid + 256;                    // valid for tid < 64
    const int r21 = 8 * (i1 >> 6) + (i1 & 7);
    const int j21 = 8 * ((i1 >> 3) & 7);
    const bool s2b = (tid < 64);
    const bool s2n = (tid >= 192 && tid < 232);   // narrow col, rows 0..39
    const int rn = tid - 192;

    // ---- S3 mapping: 4-row x 1-col4 patches, 153 items ----
    const bool s3ok = (tid < 153);
    const int r3 = 4 * (tid / 17);
    const int j3 = 4 * (tid % 17);

    // ring pixel (mag coords: rows {1,34} x cols 0..65, cols {0,65} x rows 2..33)
    int mr = 1, mc = 0;
    const bool has_ring = (tid < 196);
    if (tid < 66)       { mr = 1;         mc = tid; }
    else if (tid < 132) { mr = 34;        mc = tid - 66; }
    else if (tid < 164) { mr = tid - 130; mc = 0; }
    else if (tid < 196) { mr = tid - 162; mc = 65; }

    float gxa[8], gya[8], maga[8];
    #pragma unroll
    for (int i = 0; i < 8; i++) { gxa[i] = 0.0f; gya[i] = 0.0f; maga[i] = 0.0f; }
    float ring_m = 0.0f;

    // ---- initial prefetch: channel 0 -> bufI0 ----
    if (interior) {
        const float* base = img + (size_t)(by - 4) * IMG_W + (bx - 4);
        cp_async16(&bufI0[s1r0 * SA + s1c0], base + (size_t)s1r0 * IMG_W + s1c0);
        cp_async16(&bufI0[s1r1 * SA + s1c1], base + (size_t)s1r1 * IMG_W + s1c1);
        if (s1b2)
            cp_async16(&bufI0[s1r2 * SA + s1c2], base + (size_t)s1r2 * IMG_W + s1c2);
        asm volatile("cp.async.commit_group;");
    } else {
        for (int p = tid; p < 2880; p += NT) {
            int r = p / 72;
            int cc = p - r * 72;
            int iy = by - 4 + r, ix = bx - 4 + cc;
            float v = 0.0f;
            if (iy >= 0 && iy < IMG_H && ix >= 0 && ix < IMG_W)
                v = img[(size_t)iy * IMG_W + ix];
            bufI0[r * SA + cc] = v;
        }
    }

    #pragma unroll
    for (int c = 0; c < 3; c++) {
        float* bI = (c & 1) ? bufI1 : bufI0;

        asm volatile("cp.async.wait_group 0;");
        __syncthreads();                 // bI ready; also orders prior channel's
                                         // S4/S4r reads before this channel's writes

        // ---- prefetch next channel ----
        if (c < 2) {
            float* bN = ((c + 1) & 1) ? bufI1 : bufI0;
            const float* imn = img + (size_t)(c + 1) * (IMG_H * IMG_W);
            if (interior) {
                const float* base = imn + (size_t)(by - 4) * IMG_W + (bx - 4);
                cp_async16(&bN[s1r0 * SA + s1c0], base + (size_t)s1r0 * IMG_W + s1c0);
                cp_async16(&bN[s1r1 * SA + s1c1], base + (size_t)s1r1 * IMG_W + s1c1);
                if (s1b2)
                    cp_async16(&bN[s1r2 * SA + s1c2], base + (size_t)s1r2 * IMG_W + s1c2);
                asm volatile("cp.async.commit_group;");
            } else {
                for (int p = tid; p < 2880; p += NT) {
                    int r = p / 72;
                    int cc = p - r * 72;
                    int iy = by - 4 + r, ix = bx - 4 + cc;
                    float v = 0.0f;
                    if (iy >= 0 && iy < IMG_H && ix >= 0 && ix < IMG_W)
                        v = imn[(size_t)iy * IMG_W + ix];
                    bN[r * SA + cc] = v;
                }
            }
        }

        // ---- S2: horizontal gaussian -> bufB (40 rows x 68 cols), scalar ----
        {
            {
                const float* a = &bI[r20 * SA + j20];
                float4 v0 = *(const float4*)a;
                float4 v1 = *(const float4*)(a + 4);
                float4 v2 = *(const float4*)(a + 8);
                float w0=v0.x,w1=v0.y,w2=v0.z,w3=v0.w,w4=v1.x,w5=v1.y,w6=v1.z,w7=v1.w,
                      w8=v2.x,w9=v2.y,w10=v2.z,w11=v2.w;
                float4 o0, o1;
                o0.x = g0*w0 + g1*w1 + g2*w2 + g3*w3 + g4*w4;
                o0.y = g0*w1 + g1*w2 + g2*w3 + g3*w4 + g4*w5;
                o0.z = g0*w2 + g1*w3 + g2*w4 + g3*w5 + g4*w6;
                o0.w = g0*w3 + g1*w4 + g2*w5 + g3*w6 + g4*w7;
                o1.x = g0*w4 + g1*w5 + g2*w6 + g3*w7 + g4*w8;
                o1.y = g0*w5 + g1*w6 + g2*w7 + g3*w8 + g4*w9;
                o1.z = g0*w6 + g1*w7 + g2*w8 + g3*w9 + g4*w10;
                o1.w = g0*w7 + g1*w8 + g2*w9 + g3*w10 + g4*w11;
                *(float4*)&bufB[r20 * SBs + j20]     = o0;
                *(float4*)&bufB[r20 * SBs + j20 + 4] = o1;
            }
            if (s2b) {
                const float* a = &bI[r21 * SA + j21];
                float4 v0 = *(const float4*)a;
                float4 v1 = *(const float4*)(a + 4);
                float4 v2 = *(const float4*)(a + 8);
                float w0=v0.x,w1=v0.y,w2=v0.z,w3=v0.w,w4=v1.x,w5=v1.y,w6=v1.z,w7=v1.w,
                      w8=v2.x,w9=v2.y,w10=v2.z,w11=v2.w;
                float4 o0, o1;
                o0.x = g0*w0 + g1*w1 + g2*w2 + g3*w3 + g4*w4;
                o0.y = g0*w1 + g1*w2 + g2*w3 + g3*w4 + g4*w5;
                o0.z = g0*w2 + g1*w3 + g2*w4 + g3*w5 + g4*w6;
                o0.w = g0*w3 + g1*w4 + g2*w5 + g3*w6 + g4*w7;
                o1.x = g0*w4 + g1*w5 + g2*w6 + g3*w7 + g4*w8;
                o1.y = g0*w5 + g1*w6 + g2*w7 + g3*w8 + g4*w9;
                o1.z = g0*w6 + g1*w7 + g2*w8 + g3*w9 + g4*w10;
                o1.w = g0*w7 + g1*w8 + g2*w9 + g3*w10 + g4*w11;
                *(float4*)&bufB[r21 * SBs + j21]     = o0;
                *(float4*)&bufB[r21 * SBs + j21 + 4] = o1;
            }
            if (s2n) {
                const float* a = &bI[rn * SA + 64];
                float4 v0 = *(const float4*)a;
                float4 v1 = *(const float4*)(a + 4);
                float4 o0;
                o0.x = g0*v0.x + g1*v0.y + g2*v0.z + g3*v0.w + g4*v1.x;
                o0.y = g0*v0.y + g1*v0.z + g2*v0.w + g3*v1.x + g4*v1.y;
                o0.z = g0*v0.z + g1*v0.w + g2*v1.x + g3*v1.y + g4*v1.z;
                o0.w = g0*v0.w + g1*v1.x + g2*v1.y + g3*v1.z + g4*v1.w;
                *(float4*)&bufB[rn * SBs + 64] = o0;
            }
        }
        __syncthreads();

        // ---- S3: vertical gaussian -> bufBl (36 rows x 68 cols), 4-row patch ----
        if (s3ok) {
            const float* bcol = &bufB[r3 * SBs + j3];
            float* acol = &bufBl[r3 * SA + j3];
            if (interior) {
                // packed f32x2: 10 ops per float4 instead of 20
                ulonglong2 t0 = *(const ulonglong2*)(bcol);
                ulonglong2 t1 = *(const ulonglong2*)(bcol + 1 * SBs);
                ulonglong2 t2 = *(const ulonglong2*)(bcol + 2 * SBs);
                ulonglong2 t3 = *(const ulonglong2*)(bcol + 3 * SBs);
                ulonglong2 t4 = *(const ulonglong2*)(bcol + 4 * SBs);
                #pragma unroll
                for (int k = 0; k < 4; k++) {
                    ulonglong2 o;
                    o.x = pblur5(G0, G1, G2, G3, G4, t0.x, t1.x, t2.x, t3.x, t4.x);
                    o.y = pblur5(G0, G1, G2, G3, G4, t0.y, t1.y, t2.y, t3.y, t4.y);
                    *(ulonglong2*)(acol + k * SA) = o;
                    if (k < 3) {
                        t0 = t1; t1 = t2; t2 = t3; t3 = t4;
                        t4 = *(const ulonglong2*)(bcol + (5 + k) * SBs);
                    }
                }
            } else {
                float4 t0 = *(const float4*)(bcol);
                float4 t1 = *(const float4*)(bcol + 1 * SBs);
                float4 t2 = *(const float4*)(bcol + 2 * SBs);
                float4 t3 = *(const float4*)(bcol + 3 * SBs);
                float4 t4 = *(const float4*)(bcol + 4 * SBs);
                #pragma unroll
                for (int k = 0; k < 4; k++) {
                    float4 o = vblur5(g0, g1, g2, g3, g4, t0, t1, t2, t3, t4);
                    int iy = by - 2 + r3 + k;
                    int ixb = bx - 2 + j3;
                    float* po = &o.x;
                    #pragma unroll
                    for (int cc = 0; cc < 4; cc++) {
                        int ix = ixb + cc;
                        if (!(ix >= 0 && ix < IMG_W && iy >= 0 && iy < IMG_H)) po[cc] = 0.0f;
                    }
                    *(float4*)(acol + k * SA) = o;
                    if (k < 3) {
                        t0 = t1; t1 = t2; t2 = t3; t3 = t4;
                        t4 = *(const float4*)(bcol + (5 + k) * SBs);
                    }
                }
            }
        }
        __syncthreads();

        // ---- S4: sobel at output patch -> register accumulators ----
        // at c==2 the final mag is also stored straight to bufM (aliases bufI0,
        // whose last reads -- S2 of c==2 -- completed before the post-S2 barrier)
        {
            const float* b = &bufBl[(oy + 1) * SA + ox];
            float r0[8], r1[8], r2[8], r3v[8];
            {
                float4 lo, hi;
                lo = *(const float4*)(b);            hi = *(const float4*)(b + 4);
                r0[0]=lo.x; r0[1]=lo.y; r0[2]=lo.z; r0[3]=lo.w; r0[4]=hi.x; r0[5]=hi.y; r0[6]=hi.z; r0[7]=hi.w;
                lo = *(const float4*)(b + SA);       hi = *(const float4*)(b + SA + 4);
                r1[0]=lo.x; r1[1]=lo.y; r1[2]=lo.z; r1[3]=lo.w; r1[4]=hi.x; r1[5]=hi.y; r1[6]=hi.z; r1[7]=hi.w;
                lo = *(const float4*)(b + 2*SA);     hi = *(const float4*)(b + 2*SA + 4);
                r2[0]=lo.x; r2[1]=lo.y; r2[2]=lo.z; r2[3]=lo.w; r2[4]=hi.x; r2[5]=hi.y; r2[6]=hi.z; r2[7]=hi.w;
            }
            #pragma unroll
            for (int cc = 0; cc < 4; cc++) {
                float b00 = r0[cc+1], b01 = r0[cc+2], b02 = r0[cc+3];
                float b10 = r1[cc+1],                 b12 = r1[cc+3];
                float b20 = r2[cc+1], b21 = r2[cc+2], b22 = r2[cc+3];
                float gxv = (b00 - b02) + 2.0f * (b10 - b12) + (b20 - b22);
                float gyv = (b00 - b20) + 2.0f * (b01 - b21) + (b02 - b22);
                gxa[cc] += gxv;
                gya[cc] += gyv;
                maga[cc] += sqrtf(gxv * gxv + gyv * gyv + 1e-8f);
            }
            {
                float4 lo = *(const float4*)(b + 3*SA);
                float4 hi = *(const float4*)(b + 3*SA + 4);
                r3v[0]=lo.x; r3v[1]=lo.y; r3v[2]=lo.z; r3v[3]=lo.w; r3v[4]=hi.x; r3v[5]=hi.y; r3v[6]=hi.z; r3v[7]=hi.w;
            }
            #pragma unroll
            for (int cc = 0; cc < 4; cc++) {
                float b00 = r1[cc+1], b01 = r1[cc+2], b02 = r1[cc+3];
                float b10 = r2[cc+1],                 b12 = r2[cc+3];
                float b20 = r3v[cc+1], b21 = r3v[cc+2], b22 = r3v[cc+3];
                float gxv = (b00 - b02) + 2.0f * (b10 - b12) + (b20 - b22);
                float gyv = (b00 - b20) + 2.0f * (b01 - b21) + (b02 - b22);
                gxa[4+cc] += gxv;
                gya[4+cc] += gyv;
                maga[4+cc] += sqrtf(gxv * gxv + gyv * gyv + 1e-8f);
            }
            if (c == 2) {
                *(float4*)&bufM[(oy + 1) * SMs + ox + 4] =
                    make_float4(maga[0], maga[1], maga[2], maga[3]);
                *(float4*)&bufM[(oy + 2) * SMs + ox + 4] =
                    make_float4(maga[4], maga[5], maga[6], maga[7]);
            }
        }

        // ---- S4r: halo-ring mag pixel (register accumulated) ----
        if (has_ring) {
            const float* b = &bufBl[(mr - 1) * SA + mc];
            float b00 = b[0],      b01 = b[1],          b02 = b[2];
            float b10 = b[SA],                          b12 = b[SA + 2];
            float b20 = b[2 * SA], b21 = b[2 * SA + 1], b22 = b[2 * SA + 2];
            float gxv = (b00 - b02) + 2.0f * (b10 - b12) + (b20 - b22);
            float gyv = (b00 - b20) + 2.0f * (b01 - b21) + (b02 - b22);
            float m = sqrtf(gxv * gxv + gyv * gyv + 1e-8f);
            if (!interior) {
                int iy = by - 2 + mr, ix = bx - 1 + mc;
                if (iy < 0 || iy >= IMG_H || ix < 0 || ix >= IMG_W) m = 0.0f;
            }
            ring_m += m;
            if (c == 2) bufM[(mr - 1) * SMs + mc + 3] = ring_m;
        }
        // no end-of-channel barrier (loop-top barrier provides the ordering)
    }

    __syncthreads();   // bufM fully published before S5 reads

    // ---- S5: orientation, NMS, threshold, write ----
    // packed NMS offset table: d = dy*SMs + dx, stored as byte (d + 128)
    //   dy8 = {0,1,1,1,0,-1,-1,-1}, dx8 = {1,1,0,-1,-1,-1,0,1}
    //   d   = {1,73,72,71,-1,-73,-72,-71} -> bytes {129,201,200,199,127,55,56,57}
    const ull DTAB = 0x3938377FC7C8C981ULL;
    const float RAD2DEG = (float)(180.0 / 3.14159);

    #pragma unroll
    for (int rr = 0; rr < 2; rr++) {
        float ov[4];
        #pragma unroll
        for (int cc = 0; cc < 4; cc++) {
            int y = oy + rr, x = ox + cc;
            float m  = maga[rr*4+cc];
            float t = atan2f(gya[rr*4+cc], gxa[rr*4+cc]) * RAD2DEG + 180.0f;
            int k = (int)rintf(t / 45.0f);
            int ip = k & 7;
            int d = (int)((DTAB >> (ip * 8)) & 0xFF) - 128;
            int base = (y + 1) * SMs + (x + 4);
            float mp = bufM[base + d];
            float mn = bufM[base - d];
            bool is_max = fminf(m - mp, m - mn) > 0.0f;
            ov[cc] = (is_max && m >= 6.0f && m <= 50.0f) ? 1.0f : 0.0f;
        }
        *(float4*)(out + (size_t)(by + oy + rr) * IMG_W + bx + ox) =
            make_float4(ov[0], ov[1], ov[2], ov[3]);
    }
}

extern "C" void kernel_launch(void* const* d_in, const int* in_sizes, int n_in,
                              void* d_out, int out_size) {
    const float* img   = (const float*)d_in[0];  // [1,3,4096,4096]
    const float* gauss = (const float*)d_in[1];  // [5]
    float* out = (float*)d_out;                  // [1,1,4096,4096]

    dim3 grid(IMG_W / TW, IMG_H / TH);
    canny_kernel<<<grid, NT>>>(img, gauss, out);
}